// round 10
// baseline (speedup 1.0000x reference)
#include <cuda_runtime.h>
#include <math.h>
#include <stdint.h>

#define UNITS 1536
#define NZ 6144                 // 4*UNITS columns
#define TPB 256
#define CHUNKS 6                // 6 float4-chunks/thread -> full 24KB row per block
#define DEPTH 4                 // cp.async ring depth (rows)
#define SMEM_DYN (DEPTH * CHUNKS * TPB * 16)   // 98304 B
#define CHAR_LEN 256
#define VOCAB 80
#define N_MIX 10
#define KA1 (3 + VOCAB)         // 83
#define KX  (3 + VOCAB + UNITS) // 1619
#define NSPL 96                 // splits per matrix (one block each)
#define L_X 17                  // 96*17 = 1632 >= 1619
#define L_U 16                  // 96*16 = 1536

// ---------------- device scratch ----------------
__device__ float g_part1[NSPL * NZ];    // chain partials (W1+U1, W2, W3)
__device__ float g_part2[NSPL * NZ];    // U2 @ h2
__device__ float g_part3[NSPL * NZ];    // U3 @ h3
__device__ float g_coefpart[48][30];
__device__ float g_x2[KX];              // [inputs, w, h1n]
__device__ float g_x3[KX];              // [inputs, w, h2n]
__device__ int g_cA, g_cB, g_cC, g_cD, g_cE, g_cF;

__device__ __forceinline__ float sigf(float x) { return 1.0f / (1.0f + expf(-x)); }

__device__ __forceinline__ void cp16(unsigned sdst, const float* gsrc) {
    asm volatile("cp.async.cg.shared.global [%0], [%1], 16;" :: "r"(sdst), "l"(gsrc));
}
__device__ __forceinline__ void cp_commit() {
    asm volatile("cp.async.commit_group;" ::: "memory");
}
template<int N> __device__ __forceinline__ void cp_wait() {
    asm volatile("cp.async.wait_group %0;" :: "n"(N) : "memory");
}

// ---------------- contiguous-stream GEMV worker -----------------------------
// Block covers the FULL 6144-col row (6 chunks of 4KB); rows [k0,k0+len)
// streamed via a DEPTH-row cp.async ring. Block's gmem footprint is one
// contiguous range -> DRAM-page-friendly. Per-thread slot ownership: no
// intra-loop block barriers (wait_group orders each thread's own copies).
template<bool SEG3>
__device__ __forceinline__ void gemv_stream(
    float4* dyn,
    const float* __restrict__ W1, const float* __restrict__ U1,
    const float* __restrict__ inputs, const float* __restrict__ wprev,
    const float* __restrict__ h1,
    const float* __restrict__ M, const float* __restrict__ x,
    int Ktot, int k0, int len, int sout, float* __restrict__ part)
{
    __shared__ float xs[32];
    int t = threadIdx.x;
    if (k0 + len > Ktot) len = Ktot - k0;

    if (t < len) {
        int kk = k0 + t;
        float xv;
        if (SEG3) {
            if (kk < 3)        xv = __ldg(inputs + kk);
            else if (kk < KA1) xv = __ldg(wprev + kk - 3);
            else               xv = __ldg(h1 + kk - KA1);
        } else {
            xv = __ldg(x + kk);
        }
        xs[t] = xv;
    }
    __syncthreads();

    unsigned sbase = (unsigned)__cvta_generic_to_shared(dyn);

    int npro = (len < DEPTH) ? len : DEPTH;
    for (int i = 0; i < npro; ++i) {
        int kk = k0 + i;
        const float* rp = SEG3
            ? ((kk < KA1) ? (W1 + (size_t)kk * NZ) : (U1 + (size_t)(kk - KA1) * NZ))
            : (M + (size_t)kk * NZ);
        #pragma unroll
        for (int j = 0; j < CHUNKS; ++j)
            cp16(sbase + (unsigned)(((i * CHUNKS + j) * TPB + t) * 16),
                 rp + (j * TPB + t) * 4);
        cp_commit();
    }

    float4 acc[CHUNKS];
    #pragma unroll
    for (int j = 0; j < CHUNKS; ++j) acc[j] = make_float4(0.f, 0.f, 0.f, 0.f);

    for (int r = 0; r < len; ++r) {
        if (r + DEPTH <= len) cp_wait<DEPTH - 1>();
        else if (r + DEPTH == len + 1 || (r == 0 && len < DEPTH)) cp_wait<0>();
        int s = r & (DEPTH - 1);
        float xv = xs[r];
        #pragma unroll
        for (int j = 0; j < CHUNKS; ++j) {
            float4 v = dyn[(s * CHUNKS + j) * TPB + t];
            acc[j].x += xv * v.x; acc[j].y += xv * v.y;
            acc[j].z += xv * v.z; acc[j].w += xv * v.w;
        }
        int nr = r + DEPTH;
        if (nr < len) {
            int kk = k0 + nr;
            const float* rp = SEG3
                ? ((kk < KA1) ? (W1 + (size_t)kk * NZ) : (U1 + (size_t)(kk - KA1) * NZ))
                : (M + (size_t)kk * NZ);
            int s2 = nr & (DEPTH - 1);
            #pragma unroll
            for (int j = 0; j < CHUNKS; ++j)
                cp16(sbase + (unsigned)(((s2 * CHUNKS + j) * TPB + t) * 16),
                     rp + (j * TPB + t) * 4);
            cp_commit();
        }
    }
    #pragma unroll
    for (int j = 0; j < CHUNKS; ++j)
        *reinterpret_cast<float4*>(part + (size_t)sout * NZ + (j * TPB + t) * 4) = acc[j];
}

// ---------------- gates: reduce partials + LSTM nonlinearity (256 thr) ------
__device__ __forceinline__ void gates_body(
    int blk, const float* __restrict__ b, const float* __restrict__ c_in,
    const float* __restrict__ pA, int nsA,
    const float* __restrict__ pB, int nsB,
    float* __restrict__ out_h, float* __restrict__ xnext,
    const float* __restrict__ Wd)
{
    __shared__ float red[8][32][4];
    __shared__ float hsh[32];
    __shared__ float csh[4][30];
    int t = threadIdx.x, ul = t & 31, sg = t >> 5;   // 8 subgroups
    int u = blk * 32 + ul;

    float s0 = 0.f, s1 = 0.f, s2 = 0.f, s3 = 0.f;
    for (int s = sg; s < nsA; s += 8) {
        const float* row = pA + (size_t)s * NZ;
        s0 += row[u]; s1 += row[u + UNITS]; s2 += row[u + 2 * UNITS]; s3 += row[u + 3 * UNITS];
    }
    for (int s = sg; s < nsB; s += 8) {
        const float* row = pB + (size_t)s * NZ;
        s0 += row[u]; s1 += row[u + UNITS]; s2 += row[u + 2 * UNITS]; s3 += row[u + 3 * UNITS];
    }
    red[sg][ul][0] = s0; red[sg][ul][1] = s1; red[sg][ul][2] = s2; red[sg][ul][3] = s3;
    __syncthreads();

    if (sg == 0) {
        float zi = b[u], zf = b[u + UNITS], zg = b[u + 2 * UNITS], zo = b[u + 3 * UNITS];
        #pragma unroll
        for (int g = 0; g < 8; ++g) {
            zi += red[g][ul][0]; zf += red[g][ul][1];
            zg += red[g][ul][2]; zo += red[g][ul][3];
        }
        float c = sigf(zf) * c_in[u] + sigf(zi) * tanhf(zg);
        float h = sigf(zo) * tanhf(c);
        out_h[u] = h;
        if (xnext) xnext[u] = h;
        hsh[ul] = h;
    }

    if (Wd) {
        __syncthreads();
        if (t < 120) {                       // j = t%30, group g = t/30 (8 units each)
            int j = t % 30, g = t / 30;
            int ub = blk * 32 + g * 8;
            float s = 0.f;
            #pragma unroll
            for (int i = 0; i < 8; ++i)
                s += hsh[g * 8 + i] * __ldg(Wd + (size_t)(ub + i) * 30 + j);
            csh[g][j] = s;
        }
        __syncthreads();
        if (t < 30)
            g_coefpart[blk][t] = csh[0][t] + csh[1][t] + csh[2][t] + csh[3][t];
    }
}

// ---------------- window finisher (256 threads) ------------------------------
__device__ __forceinline__ void window_body(
    const float* __restrict__ bd, const float* __restrict__ kp,
    const float* __restrict__ sentence, const float* __restrict__ inputs)
{
    __shared__ float coef[30];
    __shared__ float alpha[N_MIX], beta[N_MIX], kap[N_MIX];
    __shared__ float phi[CHAR_LEN];
    __shared__ float wpart[8][VOCAB];
    int t = threadIdx.x, warp = t >> 5, lane = t & 31;

    if (t < 3) { g_x2[t] = inputs[t]; g_x3[t] = inputs[t]; }
    if (t < 30) {
        float s = bd[t];
        #pragma unroll
        for (int blk = 0; blk < 48; ++blk) s += g_coefpart[blk][t];
        coef[t] = s;
    }
    __syncthreads();
    if (t < N_MIX) {
        alpha[t] = expf(coef[t]);
        beta[t]  = expf(coef[N_MIX + t]);
        kap[t]   = kp[t] + expf(coef[2 * N_MIX + t]);
    }
    __syncthreads();
    {
        float u = (float)(t + 1);
        float p = 0.f;
        #pragma unroll
        for (int m = 0; m < N_MIX; ++m) {
            float d = kap[m] - u;
            p += alpha[m] * expf(-beta[m] * d * d);
        }
        phi[t] = p;
    }
    __syncthreads();
    {
        float a0 = 0.f, a1 = 0.f, a2 = 0.f;
        #pragma unroll 8
        for (int cc = 0; cc < 32; ++cc) {
            int c = warp * 32 + cc;
            float pv = phi[c];
            const float* row = sentence + (size_t)c * VOCAB;
            a0 += pv * __ldg(row + lane);
            a1 += pv * __ldg(row + 32 + lane);
            if (lane < 16) a2 += pv * __ldg(row + 64 + lane);
        }
        wpart[warp][lane]      = a0;
        wpart[warp][lane + 32] = a1;
        if (lane < 16) wpart[warp][lane + 64] = a2;
    }
    __syncthreads();
    if (t < VOCAB) {
        float s = 0.f;
        #pragma unroll
        for (int w = 0; w < 8; ++w) s += wpart[w][t];
        g_x2[3 + t] = s;
        g_x3[3 + t] = s;
    }
}

// ---------------- launch A: mega GEMV + gates1 + coef + window --------------
// bids: [0,96) W1+U1 ; [96,192) U2 ; [192,288) U3 ; [288,336) gates1 ; 336 window
__global__ void __launch_bounds__(TPB) fusedA(
    const float* __restrict__ W1, const float* __restrict__ inputs,
    const float* __restrict__ wprev, const float* __restrict__ U1, const float* __restrict__ h1,
    const float* __restrict__ U2, const float* __restrict__ h2,
    const float* __restrict__ U3, const float* __restrict__ h3,
    const float* __restrict__ b1, const float* __restrict__ c1, float* __restrict__ out,
    const float* __restrict__ Wd, const float* __restrict__ bd,
    const float* __restrict__ kappa_prev, const float* __restrict__ sentence)
{
    extern __shared__ float4 dyn[];
    int bid = blockIdx.x;
    if (bid < NSPL) {
        gemv_stream<true>(dyn, W1, U1, inputs, wprev, h1, nullptr, nullptr,
                          KX, bid * L_X, L_X, bid, g_part1);
        __syncthreads();
        if (threadIdx.x == 0) { __threadfence(); atomicAdd(&g_cA, 1); }
    } else if (bid < 2 * NSPL) {
        int sp = bid - NSPL;
        gemv_stream<false>(dyn, nullptr, nullptr, nullptr, nullptr, nullptr, U2, h2,
                           UNITS, sp * L_U, L_U, sp, g_part2);
    } else if (bid < 3 * NSPL) {
        int sp = bid - 2 * NSPL;
        gemv_stream<false>(dyn, nullptr, nullptr, nullptr, nullptr, nullptr, U3, h3,
                           UNITS, sp * L_U, L_U, sp, g_part3);
    } else if (bid < 3 * NSPL + 48) {
        int blk = bid - 3 * NSPL;
        if (threadIdx.x == 0) { while (((volatile int*)&g_cA)[0] < NSPL) __nanosleep(32); }
        __syncthreads(); __threadfence();
        gates_body(blk, b1, c1, g_part1, NSPL, nullptr, 0, out, g_x2 + KA1, Wd);
        __syncthreads();
        if (threadIdx.x == 0) { __threadfence(); atomicAdd(&g_cB, 1); }
    } else {
        if (threadIdx.x == 0) { while (((volatile int*)&g_cB)[0] < 48) __nanosleep(32); }
        __syncthreads(); __threadfence();
        window_body(bd, kappa_prev, sentence, inputs);
        __syncthreads();
        if (threadIdx.x == 0) { g_cA = 0; g_cB = 0; __threadfence(); }
    }
}

// ---------------- launch B/C: chain GEMV + gates ----------------------------
__global__ void __launch_bounds__(TPB) fusedChain(
    const float* __restrict__ W, const float* __restrict__ x,
    const float* __restrict__ pB, int nsB,
    const float* __restrict__ b, const float* __restrict__ c_in,
    float* __restrict__ out_h, float* __restrict__ xnext,
    int* __restrict__ cW, int* __restrict__ cG)
{
    extern __shared__ float4 dyn[];
    int bid = blockIdx.x;
    if (bid < NSPL) {
        gemv_stream<false>(dyn, nullptr, nullptr, nullptr, nullptr, nullptr, W, x,
                           KX, bid * L_X, L_X, bid, g_part1);
        __syncthreads();
        if (threadIdx.x == 0) { __threadfence(); atomicAdd(cW, 1); }
    } else {
        int blk = bid - NSPL;
        if (threadIdx.x == 0) { while (((volatile int*)cW)[0] < NSPL) __nanosleep(32); }
        __syncthreads(); __threadfence();
        gates_body(blk, b, c_in, g_part1, NSPL, pB, nsB, out_h, xnext, nullptr);
        __syncthreads();
        if (threadIdx.x == 0) {
            __threadfence();
            int v = atomicAdd(cG, 1);
            if (v == 47) { *cW = 0; *cG = 0; __threadfence(); }
        }
    }
}

// ---------------- launch ----------------
extern "C" void kernel_launch(void* const* d_in, const int* in_sizes, int n_in,
                              void* d_out, int out_size)
{
    const float* inputs     = (const float*)d_in[0];
    const float* h1_in      = (const float*)d_in[1];
    const float* c1_in      = (const float*)d_in[2];
    const float* h2_in      = (const float*)d_in[3];
    const float* c2_in      = (const float*)d_in[4];
    const float* h3_in      = (const float*)d_in[5];
    const float* c3_in      = (const float*)d_in[6];
    const float* w_prev     = (const float*)d_in[7];
    const float* kappa_prev = (const float*)d_in[8];
    const float* sentence   = (const float*)d_in[9];
    const float* W1 = (const float*)d_in[10];
    const float* U1 = (const float*)d_in[11];
    const float* b1 = (const float*)d_in[12];
    const float* Wd = (const float*)d_in[13];
    const float* bd = (const float*)d_in[14];
    const float* W2 = (const float*)d_in[15];
    const float* U2 = (const float*)d_in[16];
    const float* b2 = (const float*)d_in[17];
    const float* W3 = (const float*)d_in[18];
    const float* U3 = (const float*)d_in[19];
    const float* b3 = (const float*)d_in[20];
    float* out = (float*)d_out;

    // Opt-in to >48KB dynamic smem. First call is outside graph capture and
    // persists; during capture these are no-ops / harmless.
    cudaFuncSetAttribute(fusedA, cudaFuncAttributeMaxDynamicSharedMemorySize, SMEM_DYN);
    cudaFuncSetAttribute(fusedChain, cudaFuncAttributeMaxDynamicSharedMemorySize, SMEM_DYN);

    float *x2p, *x3p, *p2p, *p3p;
    cudaGetSymbolAddress((void**)&x2p, g_x2);
    cudaGetSymbolAddress((void**)&x3p, g_x3);
    cudaGetSymbolAddress((void**)&p2p, g_part2);
    cudaGetSymbolAddress((void**)&p3p, g_part3);
    int *cCp, *cDp, *cEp, *cFp;
    cudaGetSymbolAddress((void**)&cCp, g_cC);
    cudaGetSymbolAddress((void**)&cDp, g_cD);
    cudaGetSymbolAddress((void**)&cEp, g_cE);
    cudaGetSymbolAddress((void**)&cFp, g_cF);

    // A: mega GEMV (W1+U1, U2@h2, U3@h3) + gates1 + coef + window
    fusedA<<<3 * NSPL + 49, TPB, SMEM_DYN>>>(W1, inputs, w_prev, U1, h1_in,
                                             U2, h2_in, U3, h3_in,
                                             b1, c1_in, out, Wd, bd, kappa_prev, sentence);

    // B: W2 @ x2 -> part1 ; gates2 reduces part1 + part2
    fusedChain<<<NSPL + 48, TPB, SMEM_DYN>>>(W2, x2p, p2p, NSPL, b2, c2_in,
                                             out + UNITS, x3p + KA1, cCp, cDp);

    // C: W3 @ x3 -> part1 ; gates3 reduces part1 + part3
    fusedChain<<<NSPL + 48, TPB, SMEM_DYN>>>(W3, x3p, p3p, NSPL, b3, c3_in,
                                             out + 2 * UNITS, nullptr, cEp, cFp);
}

// round 11
// speedup vs baseline: 1.0442x; 1.0442x over previous
#include <cuda_runtime.h>
#include <math.h>
#include <stdint.h>

#define UNITS 1536
#define NZ 6144                 // 4*UNITS
#define TPB 256                 // 256 thr * 4 cols = 1024 cols per block
#define XT 6                    // 6 column tiles * 1024 = 6144
#define CHAR_LEN 256
#define VOCAB 80
#define N_MIX 10
#define KA1 (3 + VOCAB)         // 83
#define KX  (3 + VOCAB + UNITS) // 1619
#define NS 48                   // splits per matrix
#define L_X 34                  // rows per split, KX matrices (48*34=1632)
#define L_U 32                  // rows per split, U matrices (48*32=1536)
#define W_W (XT * NS)           // 288 worker blocks per matrix slab

// ---------------- device scratch (no allocations allowed) ----------------
__device__ float g_part1[NS * NZ];      // chain partials (W1+U1, W2, W3)
__device__ float g_part2[NS * NZ];      // U2 @ h2
__device__ float g_part3[NS * NZ];      // U3 @ h3
__device__ float g_coefpart[48][30];
__device__ float g_x2[KX];              // [inputs, w, h1n]
__device__ float g_x3[KX];              // [inputs, w, h2n]
__device__ int g_cA, g_cB, g_cC, g_cD, g_cE, g_cF;

__device__ __forceinline__ float sigf(float x) { return 1.0f / (1.0f + expf(-x)); }

// ---------------- packed f32x2 helpers (Blackwell FFMA2) --------------------
__device__ __forceinline__ unsigned long long pack2(float v) {
    unsigned long long r;
    asm("mov.b64 %0, {%1, %1};" : "=l"(r) : "r"(__float_as_uint(v)));
    return r;
}
__device__ __forceinline__ void ffma2(unsigned long long& acc,
                                      unsigned long long w, unsigned long long xx) {
    asm("fma.rn.f32x2 %0, %1, %2, %0;" : "+l"(acc) : "l"(w), "l"(xx));
}
__device__ __forceinline__ float2 unpack2(unsigned long long a) {
    unsigned lo, hi;
    asm("mov.b64 {%0, %1}, %2;" : "=r"(lo), "=r"(hi) : "l"(a));
    return make_float2(__uint_as_float(lo), __uint_as_float(hi));
}

// ---------------- GEMV worker: register LDG + FFMA2 -------------------------
// Block owns 1024 cols (thread: one float4 = two f32x2 accumulators) and
// [k0, k0+len) rows. ~3.5 issue slots per 16B: 1 LDG.128 + 2 FFMA2 + LDS.
template<bool SEG3>
__device__ __forceinline__ void gemv_reg(
    const float* __restrict__ W1, const float* __restrict__ U1,
    const float* __restrict__ inputs, const float* __restrict__ wprev,
    const float* __restrict__ h1,
    const float* __restrict__ M, const float* __restrict__ x,
    int Ktot, int k0, int len, int xt, int sout, float* __restrict__ part)
{
    __shared__ unsigned long long xs2[40];
    int t = threadIdx.x;
    int col4 = (xt * TPB + t) * 4;
    if (k0 + len > Ktot) len = Ktot - k0;

    if (t < len) {
        int kk = k0 + t;
        float xv;
        if (SEG3) {
            if (kk < 3)        xv = __ldg(inputs + kk);
            else if (kk < KA1) xv = __ldg(wprev + kk - 3);
            else               xv = __ldg(h1 + kk - KA1);
        } else {
            xv = __ldg(x + kk);
        }
        xs2[t] = pack2(xv);
    }
    __syncthreads();

    unsigned long long a0 = 0ull, a1 = 0ull;   // bits 0 == (0.f,0.f)

    auto accum = [&](const float* rowbase, int n, int xoff) {
        const float* p = rowbase + col4;
        int k = 0;
        for (; k + 8 <= n; k += 8) {
            ulonglong2 w[8];
            #pragma unroll
            for (int i = 0; i < 8; ++i)
                w[i] = *reinterpret_cast<const ulonglong2*>(p + (size_t)(k + i) * NZ);
            unsigned long long xv[8];
            #pragma unroll
            for (int i = 0; i < 8; ++i) xv[i] = xs2[xoff + k + i];
            #pragma unroll
            for (int i = 0; i < 8; ++i) {
                ffma2(a0, w[i].x, xv[i]);
                ffma2(a1, w[i].y, xv[i]);
            }
        }
        for (; k < n; ++k) {
            ulonglong2 w = *reinterpret_cast<const ulonglong2*>(p + (size_t)k * NZ);
            unsigned long long xv = xs2[xoff + k];
            ffma2(a0, w.x, xv);
            ffma2(a1, w.y, xv);
        }
    };

    int kend = k0 + len;
    if (SEG3) {
        if (k0 < KA1) {
            int rb = (kend < KA1) ? kend : KA1;
            accum(W1 + (size_t)k0 * NZ, rb - k0, 0);
        }
        if (kend > KA1) {
            int ra = (k0 > KA1) ? k0 : KA1;
            accum(U1 + (size_t)(ra - KA1) * NZ, kend - ra, ra - k0);
        }
    } else {
        accum(M + (size_t)k0 * NZ, len, 0);
    }

    float2 lo = unpack2(a0), hi = unpack2(a1);
    float4 res = make_float4(lo.x, lo.y, hi.x, hi.y);
    *reinterpret_cast<float4*>(part + (size_t)sout * NZ + col4) = res;
}

// ---------------- gates: reduce partials + LSTM nonlinearity (256 thr) ------
__device__ __forceinline__ void gates_body(
    int blk, const float* __restrict__ b, const float* __restrict__ c_in,
    const float* __restrict__ pA, int nsA,
    const float* __restrict__ pB, int nsB,
    float* __restrict__ out_h, float* __restrict__ xnext,
    const float* __restrict__ Wd)
{
    __shared__ float red[8][32][4];
    __shared__ float hsh[32];
    __shared__ float csh[4][30];
    int t = threadIdx.x, ul = t & 31, sg = t >> 5;   // 8 subgroups
    int u = blk * 32 + ul;

    float s0 = 0.f, s1 = 0.f, s2 = 0.f, s3 = 0.f;
    for (int s = sg; s < nsA; s += 8) {
        const float* row = pA + (size_t)s * NZ;
        s0 += row[u]; s1 += row[u + UNITS]; s2 += row[u + 2 * UNITS]; s3 += row[u + 3 * UNITS];
    }
    for (int s = sg; s < nsB; s += 8) {
        const float* row = pB + (size_t)s * NZ;
        s0 += row[u]; s1 += row[u + UNITS]; s2 += row[u + 2 * UNITS]; s3 += row[u + 3 * UNITS];
    }
    red[sg][ul][0] = s0; red[sg][ul][1] = s1; red[sg][ul][2] = s2; red[sg][ul][3] = s3;
    __syncthreads();

    if (sg == 0) {
        float zi = b[u], zf = b[u + UNITS], zg = b[u + 2 * UNITS], zo = b[u + 3 * UNITS];
        #pragma unroll
        for (int g = 0; g < 8; ++g) {
            zi += red[g][ul][0]; zf += red[g][ul][1];
            zg += red[g][ul][2]; zo += red[g][ul][3];
        }
        float c = sigf(zf) * c_in[u] + sigf(zi) * tanhf(zg);
        float h = sigf(zo) * tanhf(c);
        out_h[u] = h;
        if (xnext) xnext[u] = h;
        hsh[ul] = h;
    }

    if (Wd) {
        __syncthreads();
        if (t < 120) {                       // j = t%30, group g = t/30 (8 units each)
            int j = t % 30, g = t / 30;
            int ub = blk * 32 + g * 8;
            float s = 0.f;
            #pragma unroll
            for (int i = 0; i < 8; ++i)
                s += hsh[g * 8 + i] * __ldg(Wd + (size_t)(ub + i) * 30 + j);
            csh[g][j] = s;
        }
        __syncthreads();
        if (t < 30)
            g_coefpart[blk][t] = csh[0][t] + csh[1][t] + csh[2][t] + csh[3][t];
    }
}

// ---------------- window finisher (256 threads) ------------------------------
__device__ __forceinline__ void window_body(
    const float* __restrict__ bd, const float* __restrict__ kp,
    const float* __restrict__ sentence, const float* __restrict__ inputs)
{
    __shared__ float coef[30];
    __shared__ float alpha[N_MIX], beta[N_MIX], kap[N_MIX];
    __shared__ float phi[CHAR_LEN];
    __shared__ float wpart[8][VOCAB];
    int t = threadIdx.x, warp = t >> 5, lane = t & 31;

    if (t < 3) { g_x2[t] = inputs[t]; g_x3[t] = inputs[t]; }
    if (t < 30) {
        float s = bd[t];
        #pragma unroll
        for (int blk = 0; blk < 48; ++blk) s += g_coefpart[blk][t];
        coef[t] = s;
    }
    __syncthreads();
    if (t < N_MIX) {
        alpha[t] = expf(coef[t]);
        beta[t]  = expf(coef[N_MIX + t]);
        kap[t]   = kp[t] + expf(coef[2 * N_MIX + t]);
    }
    __syncthreads();
    {
        float u = (float)(t + 1);
        float p = 0.f;
        #pragma unroll
        for (int m = 0; m < N_MIX; ++m) {
            float d = kap[m] - u;
            p += alpha[m] * expf(-beta[m] * d * d);
        }
        phi[t] = p;                           // t covers 0..255 exactly
    }
    __syncthreads();
    {
        float a0 = 0.f, a1 = 0.f, a2 = 0.f;
        #pragma unroll 8
        for (int cc = 0; cc < 32; ++cc) {
            int c = warp * 32 + cc;
            float pv = phi[c];
            const float* row = sentence + (size_t)c * VOCAB;
            a0 += pv * __ldg(row + lane);
            a1 += pv * __ldg(row + 32 + lane);
            if (lane < 16) a2 += pv * __ldg(row + 64 + lane);
        }
        wpart[warp][lane]      = a0;
        wpart[warp][lane + 32] = a1;
        if (lane < 16) wpart[warp][lane + 64] = a2;
    }
    __syncthreads();
    if (t < VOCAB) {
        float s = 0.f;
        #pragma unroll
        for (int w = 0; w < 8; ++w) s += wpart[w][t];
        g_x2[3 + t] = s;
        g_x3[3 + t] = s;
    }
}

// ---------------- launch A: mega GEMV + gates1 + coef + window --------------
// bids: [0,288) W1+U1 -> part1 ; [288,576) U2 -> part2 ; [576,864) U3 -> part3
//       [864,912) gates1 ; 912 window
__global__ void __launch_bounds__(TPB) fusedA(
    const float* __restrict__ W1, const float* __restrict__ inputs,
    const float* __restrict__ wprev, const float* __restrict__ U1, const float* __restrict__ h1,
    const float* __restrict__ U2, const float* __restrict__ h2,
    const float* __restrict__ U3, const float* __restrict__ h3,
    const float* __restrict__ b1, const float* __restrict__ c1, float* __restrict__ out,
    const float* __restrict__ Wd, const float* __restrict__ bd,
    const float* __restrict__ kappa_prev, const float* __restrict__ sentence)
{
    int bid = blockIdx.x;
    if (bid < W_W) {
        int split = bid / XT, xt = bid % XT;
        gemv_reg<true>(W1, U1, inputs, wprev, h1, nullptr, nullptr,
                       KX, split * L_X, L_X, xt, split, g_part1);
        __syncthreads();
        if (threadIdx.x == 0) { __threadfence(); atomicAdd(&g_cA, 1); }
    } else if (bid < 2 * W_W) {
        int r = bid - W_W, split = r / XT, xt = r % XT;
        gemv_reg<false>(nullptr, nullptr, nullptr, nullptr, nullptr, U2, h2,
                        UNITS, split * L_U, L_U, xt, split, g_part2);
    } else if (bid < 3 * W_W) {
        int r = bid - 2 * W_W, split = r / XT, xt = r % XT;
        gemv_reg<false>(nullptr, nullptr, nullptr, nullptr, nullptr, U3, h3,
                        UNITS, split * L_U, L_U, xt, split, g_part3);
    } else if (bid < 3 * W_W + 48) {
        int blk = bid - 3 * W_W;
        if (threadIdx.x == 0) { while (((volatile int*)&g_cA)[0] < W_W) __nanosleep(32); }
        __syncthreads(); __threadfence();
        gates_body(blk, b1, c1, g_part1, NS, nullptr, 0, out, g_x2 + KA1, Wd);
        __syncthreads();
        if (threadIdx.x == 0) { __threadfence(); atomicAdd(&g_cB, 1); }
    } else {
        if (threadIdx.x == 0) { while (((volatile int*)&g_cB)[0] < 48) __nanosleep(32); }
        __syncthreads(); __threadfence();
        window_body(bd, kappa_prev, sentence, inputs);
        __syncthreads();
        if (threadIdx.x == 0) { g_cA = 0; g_cB = 0; __threadfence(); }
    }
}

// ---------------- launch B/C: chain GEMV + gates ----------------------------
__global__ void __launch_bounds__(TPB) fusedChain(
    const float* __restrict__ W, const float* __restrict__ x,
    const float* __restrict__ pB, int nsB,
    const float* __restrict__ b, const float* __restrict__ c_in,
    float* __restrict__ out_h, float* __restrict__ xnext,
    int* __restrict__ cW, int* __restrict__ cG)
{
    int bid = blockIdx.x;
    if (bid < W_W) {
        int split = bid / XT, xt = bid % XT;
        gemv_reg<false>(nullptr, nullptr, nullptr, nullptr, nullptr, W, x,
                        KX, split * L_X, L_X, xt, split, g_part1);
        __syncthreads();
        if (threadIdx.x == 0) { __threadfence(); atomicAdd(cW, 1); }
    } else {
        int blk = bid - W_W;
        if (threadIdx.x == 0) { while (((volatile int*)cW)[0] < W_W) __nanosleep(32); }
        __syncthreads(); __threadfence();
        gates_body(blk, b, c_in, g_part1, NS, pB, nsB, out_h, xnext, nullptr);
        __syncthreads();
        if (threadIdx.x == 0) {
            __threadfence();
            int v = atomicAdd(cG, 1);
            if (v == 47) { *cW = 0; *cG = 0; __threadfence(); }
        }
    }
}

// ---------------- launch ----------------
extern "C" void kernel_launch(void* const* d_in, const int* in_sizes, int n_in,
                              void* d_out, int out_size)
{
    const float* inputs     = (const float*)d_in[0];
    const float* h1_in      = (const float*)d_in[1];
    const float* c1_in      = (const float*)d_in[2];
    const float* h2_in      = (const float*)d_in[3];
    const float* c2_in      = (const float*)d_in[4];
    const float* h3_in      = (const float*)d_in[5];
    const float* c3_in      = (const float*)d_in[6];
    const float* w_prev     = (const float*)d_in[7];
    const float* kappa_prev = (const float*)d_in[8];
    const float* sentence   = (const float*)d_in[9];
    const float* W1 = (const float*)d_in[10];
    const float* U1 = (const float*)d_in[11];
    const float* b1 = (const float*)d_in[12];
    const float* Wd = (const float*)d_in[13];
    const float* bd = (const float*)d_in[14];
    const float* W2 = (const float*)d_in[15];
    const float* U2 = (const float*)d_in[16];
    const float* b2 = (const float*)d_in[17];
    const float* W3 = (const float*)d_in[18];
    const float* U3 = (const float*)d_in[19];
    const float* b3 = (const float*)d_in[20];
    float* out = (float*)d_out;

    float *x2p, *x3p, *p2p, *p3p;
    cudaGetSymbolAddress((void**)&x2p, g_x2);
    cudaGetSymbolAddress((void**)&x3p, g_x3);
    cudaGetSymbolAddress((void**)&p2p, g_part2);
    cudaGetSymbolAddress((void**)&p3p, g_part3);
    int *cCp, *cDp, *cEp, *cFp;
    cudaGetSymbolAddress((void**)&cCp, g_cC);
    cudaGetSymbolAddress((void**)&cDp, g_cD);
    cudaGetSymbolAddress((void**)&cEp, g_cE);
    cudaGetSymbolAddress((void**)&cFp, g_cF);

    // A: mega GEMV (W1+U1, U2@h2, U3@h3) + gates1 + coef + window
    fusedA<<<3 * W_W + 49, TPB>>>(W1, inputs, w_prev, U1, h1_in,
                                  U2, h2_in, U3, h3_in,
                                  b1, c1_in, out, Wd, bd, kappa_prev, sentence);

    // B: W2 @ x2 -> part1 ; gates2 reduces part1 + part2
    fusedChain<<<W_W + 48, TPB>>>(W2, x2p, p2p, NS, b2, c2_in,
                                  out + UNITS, x3p + KA1, cCp, cDp);

    // C: W3 @ x3 -> part1 ; gates3 reduces part1 + part3
    fusedChain<<<W_W + 48, TPB>>>(W3, x3p, p3p, NS, b3, c3_in,
                                  out + 2 * UNITS, nullptr, cEp, cFp);
}